// round 10
// baseline (speedup 1.0000x reference)
#include <cuda_runtime.h>
#include <cuda_bf16.h>

// ResidualAverageBlock, fused persistent kernel.
//   Phase A: s[32] = sum_n w_n * x_n ; sw = sum_n w_n   (per-block partials)
//   grid-barrier (replay-safe)
//   Phase B (last block): h = relu((s@Win^T)/sw); x_ = h@Wout^T
//   Phase C (all blocks): out = x + broadcast(x_), LIFO order over the SAME rows
//            this block reduced in phase A (L2/L1 temporal reuse), with
//            evict-first loads/stores to avoid polluting L2.

#define BLOCKS_A 296
#define TPB_A    512
#define WARPS_A  (TPB_A / 32)             // 16
#define TOTAL_WARPS (BLOCKS_A * WARPS_A)  // 4736

__device__ float g_part[33 * BLOCKS_A];   // [c][b]
__device__ float g_res[32];
__device__ int   g_arrive  = 0;           // reset by last block each run
__device__ int   g_release = 0;           // monotone across graph replays

__global__ __launch_bounds__(TPB_A, 2)
void fused_kernel(const float* __restrict__ x, const float* __restrict__ w,
                  const float* __restrict__ Win, const float* __restrict__ Wout,
                  float* __restrict__ out, int N)
{
    const int tid  = threadIdx.x;
    const int lane = tid & 31;
    const int warp = tid >> 5;
    const int sub  = lane & 7;     // column group: cols 4*sub .. 4*sub+3
    const int rg   = lane >> 3;    // row offset within 4-row group

    __shared__ float4 sh4[WARPS_A][8];
    __shared__ float  shw[WARPS_A];
    __shared__ float  red[33][8];
    __shared__ float  s_[33];
    __shared__ float  h_[128];
    __shared__ float4 r4s[8];
    __shared__ int    sh_last, sh_r0;

    const int R = (N + TOTAL_WARPS - 1) / TOTAL_WARPS;    // 212 rows per warp

    // ---------------- Phase A: weighted column reduce ----------------
    {
        const float4* __restrict__ x4 = reinterpret_cast<const float4*>(x);
        const int gw = blockIdx.x * WARPS_A + warp;
        int row      = gw * R;
        const int r1 = min(row + R, N);

        float4 acc = make_float4(0.f, 0.f, 0.f, 0.f);
        float  accw = 0.f;

        for (; row + 16 <= r1; row += 16) {
            #pragma unroll
            for (int u = 0; u < 4; ++u) {
                int r = row + rg + (u << 2);
                float  wv = __ldg(&w[r]);
                float4 xv = __ldg(&x4[r * 8 + sub]);
                acc.x = fmaf(wv, xv.x, acc.x);
                acc.y = fmaf(wv, xv.y, acc.y);
                acc.z = fmaf(wv, xv.z, acc.z);
                acc.w = fmaf(wv, xv.w, acc.w);
                accw += wv;
            }
        }
        if (row < r1) {
            #pragma unroll
            for (int u = 0; u < 4; ++u) {
                int r = row + rg + (u << 2);
                if (r < r1) {
                    float  wv = __ldg(&w[r]);
                    float4 xv = __ldg(&x4[r * 8 + sub]);
                    acc.x = fmaf(wv, xv.x, acc.x);
                    acc.y = fmaf(wv, xv.y, acc.y);
                    acc.z = fmaf(wv, xv.z, acc.z);
                    acc.w = fmaf(wv, xv.w, acc.w);
                    accw += wv;
                }
            }
        }

        // reduce over rg (lanes differing in bits 3,4); rows distinct per thread,
        // duplicated only across sub -> accw needs no correction.
        #pragma unroll
        for (int off = 8; off < 32; off <<= 1) {
            acc.x += __shfl_xor_sync(0xFFFFFFFFu, acc.x, off);
            acc.y += __shfl_xor_sync(0xFFFFFFFFu, acc.y, off);
            acc.z += __shfl_xor_sync(0xFFFFFFFFu, acc.z, off);
            acc.w += __shfl_xor_sync(0xFFFFFFFFu, acc.w, off);
            accw  += __shfl_xor_sync(0xFFFFFFFFu, accw,  off);
        }
        if (lane < 8)  sh4[warp][lane] = acc;
        if (lane == 0) shw[warp] = accw;
    }
    __syncthreads();

    if (tid < 32) {
        float v = 0.f;
        #pragma unroll
        for (int q = 0; q < WARPS_A; ++q)
            v += reinterpret_cast<const float*>(&sh4[q][tid >> 2])[tid & 3];
        g_part[tid * BLOCKS_A + blockIdx.x] = v;
    } else if (tid == 32) {
        float v = 0.f;
        #pragma unroll
        for (int q = 0; q < WARPS_A; ++q) v += shw[q];
        g_part[32 * BLOCKS_A + blockIdx.x] = v;
    }
    if (tid < 33) __threadfence();     // push g_part to L2 before arriving
    __syncthreads();

    // ---------------- grid barrier (replay-safe) ----------------
    if (tid == 0) {
        sh_r0 = *(volatile int*)&g_release;
        __threadfence();
        int t = atomicAdd(&g_arrive, 1);
        sh_last = (t == BLOCKS_A - 1);
    }
    __syncthreads();

    if (sh_last) {
        // ---------------- Phase B: finish reduce + tiny MLP ----------------
        if (tid < 264) {                       // 33 cols x 8 sub-reducers
            int c = tid >> 3, k = tid & 7;
            float a = 0.f;
            #pragma unroll 4
            for (int b = k; b < BLOCKS_A; b += 8)
                a += __ldcg(&g_part[c * BLOCKS_A + b]);
            red[c][k] = a;
        }
        __syncthreads();
        if (tid < 33) {
            float a = 0.f;
            #pragma unroll
            for (int k = 0; k < 8; ++k) a += red[tid][k];
            s_[tid] = a;
        }
        __syncthreads();
        if (tid < 128) {
            float inv = 1.f / s_[32];
            float d = 0.f;
            #pragma unroll
            for (int i = 0; i < 32; ++i) d = fmaf(s_[i], Win[tid * 32 + i], d);
            h_[tid] = fmaxf(d * inv, 0.f);
        }
        __syncthreads();
        if (tid < 32) {
            float d = 0.f;
            #pragma unroll
            for (int j = 0; j < 128; ++j) d = fmaf(h_[j], Wout[tid * 128 + j], d);
            g_res[tid] = d;
            __threadfence();
        }
        __syncthreads();
        if (tid == 0) {
            g_arrive = 0;                      // reset for next graph replay
            __threadfence();
            atomicAdd(&g_release, 1);          // monotone release
        }
    } else {
        if (tid == 0) {
            while (*(volatile int*)&g_release == sh_r0) __nanosleep(64);
        }
        __syncthreads();
        __threadfence();
    }

    // ---------------- Phase C: out = x + broadcast(x_) ----------------
    // LIFO over the SAME rows this block reduced in phase A: most-recently-read
    // lines are still in L2/L1. Evict-first loads (last use) + evict-first
    // stores (don't let out writes evict x other blocks still need).
    if (tid < 8) r4s[tid] = __ldcg(reinterpret_cast<const float4*>(g_res) + tid);
    __syncthreads();

    {
        const float4* __restrict__ xr = reinterpret_cast<const float4*>(x);
        float4* __restrict__ ow       = reinterpret_cast<float4*>(out);
        const int n4     = N * 8;
        const int chunkC = R * WARPS_A * 8;                 // same rows as phase A
        const int start  = blockIdx.x * chunkC;
        const int end    = min(start + chunkC, n4);
        const int count  = max(end - start, 0);
        const int nFull  = count / TPB_A;
        const int rem    = count - nFull * TPB_A;

        const float4 rv = r4s[tid & 7];   // i%8 == tid%8 (start, TPB both mult of 8)

        // partial (highest addresses) first
        if (rem && tid < rem) {
            int i = start + nFull * TPB_A + tid;
            float4 v = __ldcs(&xr[i]);
            v.x += rv.x; v.y += rv.y; v.z += rv.z; v.w += rv.w;
            __stcs(&ow[i], v);
        }

        int k = nFull;
        for (; k >= 8; k -= 8) {
            int ib = start + (k - 8) * TPB_A + tid;
            float4 v0 = __ldcs(&xr[ib + 7 * TPB_A]);
            float4 v1 = __ldcs(&xr[ib + 6 * TPB_A]);
            float4 v2 = __ldcs(&xr[ib + 5 * TPB_A]);
            float4 v3 = __ldcs(&xr[ib + 4 * TPB_A]);
            float4 v4 = __ldcs(&xr[ib + 3 * TPB_A]);
            float4 v5 = __ldcs(&xr[ib + 2 * TPB_A]);
            float4 v6 = __ldcs(&xr[ib + 1 * TPB_A]);
            float4 v7 = __ldcs(&xr[ib + 0 * TPB_A]);
            v0.x += rv.x; v0.y += rv.y; v0.z += rv.z; v0.w += rv.w;
            v1.x += rv.x; v1.y += rv.y; v1.z += rv.z; v1.w += rv.w;
            v2.x += rv.x; v2.y += rv.y; v2.z += rv.z; v2.w += rv.w;
            v3.x += rv.x; v3.y += rv.y; v3.z += rv.z; v3.w += rv.w;
            v4.x += rv.x; v4.y += rv.y; v4.z += rv.z; v4.w += rv.w;
            v5.x += rv.x; v5.y += rv.y; v5.z += rv.z; v5.w += rv.w;
            v6.x += rv.x; v6.y += rv.y; v6.z += rv.z; v6.w += rv.w;
            v7.x += rv.x; v7.y += rv.y; v7.z += rv.z; v7.w += rv.w;
            __stcs(&ow[ib + 7 * TPB_A], v0);
            __stcs(&ow[ib + 6 * TPB_A], v1);
            __stcs(&ow[ib + 5 * TPB_A], v2);
            __stcs(&ow[ib + 4 * TPB_A], v3);
            __stcs(&ow[ib + 3 * TPB_A], v4);
            __stcs(&ow[ib + 2 * TPB_A], v5);
            __stcs(&ow[ib + 1 * TPB_A], v6);
            __stcs(&ow[ib + 0 * TPB_A], v7);
        }
        for (; k >= 1; --k) {
            int i = start + (k - 1) * TPB_A + tid;
            float4 v = __ldcs(&xr[i]);
            v.x += rv.x; v.y += rv.y; v.z += rv.z; v.w += rv.w;
            __stcs(&ow[i], v);
        }
    }
}

extern "C" void kernel_launch(void* const* d_in, const int* in_sizes, int n_in,
                              void* d_out, int out_size)
{
    const float* x    = (const float*)d_in[0];   // [N,32]
    const float* w    = (const float*)d_in[1];   // [N,1]
    const float* Win  = (const float*)d_in[2];   // [128,32]
    const float* Wout = (const float*)d_in[3];   // [32,128]
    float* out        = (float*)d_out;           // [N,32]

    const int N = in_sizes[1];                   // 1,000,000

    fused_kernel<<<BLOCKS_A, TPB_A>>>(x, w, Win, Wout, out, N);
}